// round 7
// baseline (speedup 1.0000x reference)
#include <cuda_runtime.h>
#include <cstdint>

#define TEXD   1024
#define TEXP   1025
#define OUTC   16
#define INC    32

// ---- conv GEMM geometry ----
#define XT        256          // pixels per x-strip (8 warps x 32 px)
#define XSTRIPS   5
#define YSPLIT    29
#define ROWS_PER  36           // 29*36 = 1044 >= 1025
#define PITCH_B   1056         // 264 floats per channel row (pad)
#define PLANE_B   33792        // 32 channels * 1056 B
#define NPLANES   5
#define PL_OFF    32768        // B fragments occupy [0, 32768)
#define SMEM_CONV (PL_OFF + NPLANES * PLANE_B)   // 201728 B

__device__ float g_filtB[8192];             // prepacked tf32 B fragments
__device__ float g_h2[64];
__device__ float g_tex[TEXP * TEXP * OUTC]; // [y][x][o] channel-last

// ------------------------------ helpers -----------------------------------
__device__ __forceinline__ uint32_t smem_u32(const void* p) {
    uint32_t a;
    asm("{ .reg .u64 t; cvta.to.shared.u64 t, %1; cvt.u32.u64 %0, t; }" : "=r"(a) : "l"(p));
    return a;
}
__device__ __forceinline__ uint32_t f2tf32(float f) {
    uint32_t u;
    asm("cvt.rna.tf32.f32 %0, %1;" : "=r"(u) : "f"(f));
    return u;
}

#define MMA8(C, A0, A1, A2, A3, B0, B1)                                       \
    asm volatile("mma.sync.aligned.m16n8k8.row.col.f32.tf32.tf32.f32 "        \
                 "{%0,%1,%2,%3}, {%4,%5,%6,%7}, {%8,%9}, {%0,%1,%2,%3};"      \
                 : "+f"((C)[0]), "+f"((C)[1]), "+f"((C)[2]), "+f"((C)[3])     \
                 : "r"(A0), "r"(A1), "r"(A2), "r"(A3), "r"(B0), "r"(B1))

#define LDS32(dst, addr) \
    asm("ld.shared.b32 %0, [%1];" : "=r"(dst) : "r"(addr))

// ---------------------------------------------------------------------------
// Kernel 1a: MLP layers 1-2
// ---------------------------------------------------------------------------
__global__ void mlp12_kernel(const float* __restrict__ expr,
                             const float* __restrict__ W1, const float* __restrict__ b1,
                             const float* __restrict__ W2, const float* __restrict__ b2)
{
    __shared__ float sx[76];
    __shared__ float h1[128];
    const int tid = threadIdx.x;

    if (tid < 76) sx[tid] = expr[tid];
    __syncthreads();
    if (tid < 128) {
        float a = b1[tid];
        const float* w = W1 + tid * 76;
        #pragma unroll 4
        for (int k = 0; k < 76; ++k) a = fmaf(w[k], sx[k], a);
        h1[tid] = (a >= 0.f) ? a : 0.02f * a;
    }
    __syncthreads();
    if (tid < 64) {
        float a = b2[tid];
        const float* w = W2 + tid * 128;
        #pragma unroll 4
        for (int k = 0; k < 128; ++k) a = fmaf(w[k], h1[k], a);
        g_h2[tid] = (a >= 0.f) ? a : 0.02f * a;
    }
}

// ---------------------------------------------------------------------------
// Kernel 1b: MLP layer 3 (warp per output) -> prepacked tf32 B fragments.
// f index m = o*512 + c*16 + ky*4 + kx.
// kstep j covers g = 2j, 2j+1 (g = c*4 + ky); within k8:
//   kl = kk     -> (hib = kk>>1 selects g = 2j+hib, kx = (kk&1)*2)
//   kl = kk + 4 -> same g, kx + 1
// B frag (m16n8k8 col): b0 = B[k=lane&3][n=lane>>2], b1 = B[k+4][n].
// float4 {b0_n, b1_n, b0_n+8, b1_n+8} at g_filtB[(j*32+lane)*4 + comp].
// ---------------------------------------------------------------------------
__global__ void filt_kernel(const float* __restrict__ W3, const float* __restrict__ b3)
{
    const int lane = threadIdx.x & 31;
    const int warp = threadIdx.x >> 5;
    const int m    = blockIdx.x * 8 + warp;

    const float* w = W3 + m * 64;
    float v = w[lane] * g_h2[lane] + w[lane + 32] * g_h2[lane + 32];
    #pragma unroll
    for (int s = 16; s > 0; s >>= 1) v += __shfl_xor_sync(0xFFFFFFFFu, v, s);

    if (lane == 0) {
        float a = tanhf(v + b3[m]);
        int o  = m >> 9;
        int r  = m & 511;
        int c  = r >> 4;
        int t  = r & 15;
        int ky = t >> 2;
        int kx = t & 3;
        int g   = c * 4 + ky;
        int j   = g >> 1;
        int hib = g & 1;
        int kk  = (hib << 1) | (kx >> 1);
        int ln  = ((o & 7) << 2) | kk;
        int cmp = (kx & 1) | ((o >> 3) << 1);
        g_filtB[((j * 32 + ln) << 2) | cmp] = __uint_as_float(f2tf32(a));
    }
}

// ---------------------------------------------------------------------------
// stage one data row Y into its ring plane (tf32-converted, border-zeroed)
// plane layout: [c][s], s = gx - (x0-2), pitch 1056 B per channel
// ---------------------------------------------------------------------------
__device__ __forceinline__ void stage_row(const float* __restrict__ data,
                                          char* plane, int x0, int Y, int tid)
{
    const bool yok = (unsigned)Y < 1024u;
    #pragma unroll 1
    for (int t = tid; t < 32 * 130; t += 256) {
        int c  = t / 130;
        int s2 = t - c * 130;
        int gx = x0 - 2 + 2 * s2;
        float vx = 0.f, vy = 0.f;
        if (yok) {
            const float* p = data + ((size_t)c << 20) + ((size_t)Y << 10) + gx;
            if ((unsigned)gx < 1024u)       vx = p[0];
            if ((unsigned)(gx + 1) < 1024u) vy = p[1];
        }
        uint2 ov;
        ov.x = f2tf32(vx);
        ov.y = f2tf32(vy);
        *(uint2*)(plane + c * PITCH_B + s2 * 8) = ov;
    }
}

// ---------------------------------------------------------------------------
// Kernel 2: tf32 mma.sync implicit-GEMM conv (32ch->16ch, 4x4, pad 2).
// grid = (5, 29), 256 threads. Warp w covers pixels [x0+32w, x0+32w+32).
// Per output row y: 64 k-steps, plane ring of 5 data rows.
// A loads are scalar LDS (pair addresses have per-lane parity -> no v2).
// ---------------------------------------------------------------------------
__global__ void __launch_bounds__(256, 1)
conv_kernel(const float* __restrict__ data)
{
    extern __shared__ char smem[];
    float* sB = (float*)smem;
    const uint32_t sbase = smem_u32(smem);
    const int tid  = threadIdx.x;
    const int warp = tid >> 5;
    const int lane = tid & 31;

    const int x0 = blockIdx.x * XT;
    const int y0 = blockIdx.y * ROWS_PER;
    const int y1 = min(y0 + ROWS_PER - 1, TEXP - 1);

    // B fragments -> smem
    for (int i = tid; i < 8192; i += 256) sB[i] = g_filtB[i];

    // prologue: planes for data rows y0-2 .. y0+1   (slot(Y) = (Y+10)%5)
    for (int pp = 0; pp < 4; ++pp) {
        int Y = y0 - 2 + pp;
        stage_row(data, smem + PL_OFF + ((Y + 10) % 5) * PLANE_B, x0, Y, tid);
    }
    __syncthreads();

    // per-thread fragment constants
    const int kk  = lane & 3;
    const int r   = lane >> 2;
    const int hib = kk >> 1;             // selects group g = 2j + hib
    const uint32_t xoff  = (uint32_t)(warp * 32 + ((kk & 1) << 1) + r) * 4u;
    const uint32_t bfrag = sbase + (uint32_t)(lane << 4);

    for (int y = y0; y <= y1; ++y) {
        const uint32_t pE0 = sbase + PL_OFF + (uint32_t)((y - 2 + hib + 10) % 5) * PLANE_B + xoff;
        const uint32_t pO0 = sbase + PL_OFF + (uint32_t)((y     + hib + 10) % 5) * PLANE_B + xoff;

        float acc[16];
        #pragma unroll
        for (int i = 0; i < 16; ++i) acc[i] = 0.f;

        uint32_t pE = pE0, pO = pO0, bp = bfrag;

        #pragma unroll 8
        for (int u = 0; u < 32; ++u) {
            uint32_t a0, a1, a2, a3, b0, b1, b2, b3;

            // ---- kstep j = 2u (ky = hib), channel c = u ----
            asm("ld.shared.v4.b32 {%0,%1,%2,%3}, [%4];"
                : "=r"(b0), "=r"(b1), "=r"(b2), "=r"(b3) : "r"(bp));
            LDS32(a0, pE);       LDS32(a2, pE + 4);
            LDS32(a1, pE + 32);  LDS32(a3, pE + 36);
            MMA8(acc + 0, a0, a1, a2, a3, b0, b1);
            MMA8(acc + 4, a0, a1, a2, a3, b2, b3);
            LDS32(a0, pE + 64);  LDS32(a2, pE + 68);
            LDS32(a1, pE + 96);  LDS32(a3, pE + 100);
            MMA8(acc + 8,  a0, a1, a2, a3, b0, b1);
            MMA8(acc + 12, a0, a1, a2, a3, b2, b3);

            // ---- kstep j = 2u+1 (ky = 2 + hib), same channel ----
            asm("ld.shared.v4.b32 {%0,%1,%2,%3}, [%4];"
                : "=r"(b0), "=r"(b1), "=r"(b2), "=r"(b3) : "r"(bp + 512));
            LDS32(a0, pO);       LDS32(a2, pO + 4);
            LDS32(a1, pO + 32);  LDS32(a3, pO + 36);
            MMA8(acc + 0, a0, a1, a2, a3, b0, b1);
            MMA8(acc + 4, a0, a1, a2, a3, b2, b3);
            LDS32(a0, pO + 64);  LDS32(a2, pO + 68);
            LDS32(a1, pO + 96);  LDS32(a3, pO + 100);
            MMA8(acc + 8,  a0, a1, a2, a3, b0, b1);
            MMA8(acc + 12, a0, a1, a2, a3, b2, b3);

            pE += PITCH_B;
            pO += PITCH_B;
            bp += 1024;
        }

        // ---- store row y (channel-last); C frag rows r/r+8, cols 2kk,2kk+1
        {
            const int xb = x0 + warp * 32 + r;
            const size_t rowbase = (size_t)y * TEXP;
            #pragma unroll
            for (int mt = 0; mt < 2; ++mt) {
                #pragma unroll
                for (int rr = 0; rr < 2; ++rr) {
                    int x = xb + mt * 16 + rr * 8;
                    if (x < TEXP) {
                        float* dst = g_tex + (rowbase + x) * OUTC + 2 * kk;
                        *(float2*)dst       = make_float2(acc[mt * 8 + rr * 2],
                                                          acc[mt * 8 + rr * 2 + 1]);
                        *(float2*)(dst + 8) = make_float2(acc[mt * 8 + 4 + rr * 2],
                                                          acc[mt * 8 + 4 + rr * 2 + 1]);
                    }
                }
            }
        }
        __syncthreads();    // all reads of ring slot (y+2)%5's old row done
        {
            int Y = y + 2;
            stage_row(data, smem + PL_OFF + ((Y + 10) % 5) * PLANE_B, x0, Y, tid);
        }
        __syncthreads();    // plane y+2 committed for next row
    }
}

// ---------------------------------------------------------------------------
// Kernel 3: bilinear grid sample (border, align_corners=False)
// ---------------------------------------------------------------------------
__global__ void sample_kernel(const float* __restrict__ uv, float* __restrict__ out)
{
    int p = blockIdx.x * blockDim.x + threadIdx.x;
    if (p >= TEXD * TEXD) return;

    float x = uv[p];
    float y = uv[(TEXD * TEXD) + p];

    float ix = ((x + 1.f) * (float)TEXP - 1.f) * 0.5f;
    float iy = ((y + 1.f) * (float)TEXP - 1.f) * 0.5f;
    ix = fminf(fmaxf(ix, 0.f), (float)(TEXP - 1));
    iy = fminf(fmaxf(iy, 0.f), (float)(TEXP - 1));

    float fx0 = floorf(ix), fy0 = floorf(iy);
    float wx = ix - fx0, wy = iy - fy0;
    int xi0 = (int)fx0, yi0 = (int)fy0;
    int xi1 = min(xi0 + 1, TEXP - 1);
    int yi1 = min(yi0 + 1, TEXP - 1);

    const float4* t00 = (const float4*)&g_tex[(yi0 * TEXP + xi0) * OUTC];
    const float4* t01 = (const float4*)&g_tex[(yi0 * TEXP + xi1) * OUTC];
    const float4* t10 = (const float4*)&g_tex[(yi1 * TEXP + xi0) * OUTC];
    const float4* t11 = (const float4*)&g_tex[(yi1 * TEXP + xi1) * OUTC];

    float w00 = (1.f - wx) * (1.f - wy);
    float w01 = wx * (1.f - wy);
    float w10 = (1.f - wx) * wy;
    float w11 = wx * wy;

    #pragma unroll
    for (int v = 0; v < 4; ++v) {
        float4 a = t00[v], b = t01[v], cc = t10[v], dd = t11[v];
        float r0 = a.x * w00 + b.x * w01 + cc.x * w10 + dd.x * w11;
        float r1 = a.y * w00 + b.y * w01 + cc.y * w10 + dd.y * w11;
        float r2 = a.z * w00 + b.z * w01 + cc.z * w10 + dd.z * w11;
        float r3 = a.w * w00 + b.w * w01 + cc.w * w10 + dd.w * w11;
        out[(v * 4 + 0) * (TEXD * TEXD) + p] = r0;
        out[(v * 4 + 1) * (TEXD * TEXD) + p] = r1;
        out[(v * 4 + 2) * (TEXD * TEXD) + p] = r2;
        out[(v * 4 + 3) * (TEXD * TEXD) + p] = r3;
    }
}

// ---------------------------------------------------------------------------
extern "C" void kernel_launch(void* const* d_in, const int* in_sizes, int n_in,
                              void* d_out, int out_size)
{
    const float* expr = (const float*)d_in[0];
    const float* uv   = (const float*)d_in[2];
    const float* data = (const float*)d_in[3];
    const float* W1   = (const float*)d_in[4];
    const float* b1   = (const float*)d_in[5];
    const float* W2   = (const float*)d_in[6];
    const float* b2   = (const float*)d_in[7];
    const float* W3   = (const float*)d_in[8];
    const float* b3   = (const float*)d_in[9];
    float* out = (float*)d_out;

    cudaFuncSetAttribute(conv_kernel, cudaFuncAttributeMaxDynamicSharedMemorySize,
                         SMEM_CONV);

    mlp12_kernel<<<1, 128>>>(expr, W1, b1, W2, b2);
    filt_kernel<<<1024, 256>>>(W3, b3);

    dim3 cgrid(XSTRIPS, YSPLIT);
    conv_kernel<<<cgrid, 256, SMEM_CONV>>>(data);

    sample_kernel<<<(TEXD * TEXD + 255) / 256, 256>>>(uv, out);
}

// round 8
// speedup vs baseline: 1.7857x; 1.7857x over previous
#include <cuda_runtime.h>
#include <cstdint>

#define TEXD   1024
#define TEXP   1025
#define OUTC   16
#define INC    32

// ---- conv GEMM geometry ----
#define XT        256          // pixels per x-strip (8 warps x 32 px)
#define XSTRIPS   5
#define YSPLIT    29
#define ROWS_PER  36           // 29*36 = 1044 >= 1025
#define PITCH_B   1056         // 264 floats per channel row (pad)
#define PLANE_B   33792        // 32 channels * 1056 B
#define NPLANES   5
#define PL_OFF    32768        // B fragments occupy [0, 32768)
#define SMEM_CONV (PL_OFF + NPLANES * PLANE_B)   // 201728 B
#define NTASK     4160         // 32 ch * 130 float2 per plane
#define NK        17           // ceil(4160/256)

__device__ float g_filtB[8192];             // prepacked tf32 B fragments
__device__ float g_h2[64];
__device__ float g_tex[TEXP * TEXP * OUTC]; // [y][x][o] channel-last

// ------------------------------ helpers -----------------------------------
__device__ __forceinline__ uint32_t smem_u32(const void* p) {
    uint32_t a;
    asm("{ .reg .u64 t; cvta.to.shared.u64 t, %1; cvt.u32.u64 %0, t; }" : "=r"(a) : "l"(p));
    return a;
}
__device__ __forceinline__ uint32_t f2tf32(float f) {
    uint32_t u;
    asm("cvt.rna.tf32.f32 %0, %1;" : "=r"(u) : "f"(f));
    return u;
}

#define MMA8(C, A0, A1, A2, A3, B0, B1)                                       \
    asm volatile("mma.sync.aligned.m16n8k8.row.col.f32.tf32.tf32.f32 "        \
                 "{%0,%1,%2,%3}, {%4,%5,%6,%7}, {%8,%9}, {%0,%1,%2,%3};"      \
                 : "+f"((C)[0]), "+f"((C)[1]), "+f"((C)[2]), "+f"((C)[3])     \
                 : "r"(A0), "r"(A1), "r"(A2), "r"(A3), "r"(B0), "r"(B1))

#define LDS32(dst, addr) \
    asm("ld.shared.b32 %0, [%1];" : "=r"(dst) : "r"(addr))

// ---------------------------------------------------------------------------
// Kernel 1a: MLP layers 1-2
// ---------------------------------------------------------------------------
__global__ void mlp12_kernel(const float* __restrict__ expr,
                             const float* __restrict__ W1, const float* __restrict__ b1,
                             const float* __restrict__ W2, const float* __restrict__ b2)
{
    __shared__ float sx[76];
    __shared__ float h1[128];
    const int tid = threadIdx.x;

    if (tid < 76) sx[tid] = expr[tid];
    __syncthreads();
    if (tid < 128) {
        float a = b1[tid];
        const float* w = W1 + tid * 76;
        #pragma unroll 4
        for (int k = 0; k < 76; ++k) a = fmaf(w[k], sx[k], a);
        h1[tid] = (a >= 0.f) ? a : 0.02f * a;
    }
    __syncthreads();
    if (tid < 64) {
        float a = b2[tid];
        const float* w = W2 + tid * 128;
        #pragma unroll 4
        for (int k = 0; k < 128; ++k) a = fmaf(w[k], h1[k], a);
        g_h2[tid] = (a >= 0.f) ? a : 0.02f * a;
    }
}

// ---------------------------------------------------------------------------
// Kernel 1b: MLP layer 3 (warp per output) -> prepacked tf32 B fragments.
// (mapping verified in round 7: rel_err 2.9e-4)
// ---------------------------------------------------------------------------
__global__ void filt_kernel(const float* __restrict__ W3, const float* __restrict__ b3)
{
    const int lane = threadIdx.x & 31;
    const int warp = threadIdx.x >> 5;
    const int m    = blockIdx.x * 8 + warp;

    const float* w = W3 + m * 64;
    float v = w[lane] * g_h2[lane] + w[lane + 32] * g_h2[lane + 32];
    #pragma unroll
    for (int s = 16; s > 0; s >>= 1) v += __shfl_xor_sync(0xFFFFFFFFu, v, s);

    if (lane == 0) {
        float a = tanhf(v + b3[m]);
        int o  = m >> 9;
        int r  = m & 511;
        int c  = r >> 4;
        int t  = r & 15;
        int ky = t >> 2;
        int kx = t & 3;
        int g   = c * 4 + ky;
        int j   = g >> 1;
        int hib = g & 1;
        int kk  = (hib << 1) | (kx >> 1);
        int ln  = ((o & 7) << 2) | kk;
        int cmp = (kx & 1) | ((o >> 3) << 1);
        g_filtB[((j * 32 + ln) << 2) | cmp] = __uint_as_float(f2tf32(a));
    }
}

// ---------------------------------------------------------------------------
// staging: batched load of one data row into registers (MLP ~34), then STS.
// task t = tid + 256k: c = t/130, s2 = t%130, gx = x0-2+2*s2.
// ---------------------------------------------------------------------------
__device__ __forceinline__ void stage_load(const float* __restrict__ data,
                                           int x0, int Y, int tid,
                                           float* vx, float* vy)
{
    const bool yok = (unsigned)Y < 1024u;
    #pragma unroll
    for (int k = 0; k < NK; ++k) {
        int t = tid + 256 * k;
        float a = 0.f, b = 0.f;
        if (t < NTASK && yok) {
            int c  = t / 130;
            int s2 = t - c * 130;
            int gx = x0 - 2 + 2 * s2;
            const float* p = data + ((size_t)c << 20) + ((size_t)Y << 10) + gx;
            if ((unsigned)gx < 1024u)       a = __ldg(p);
            if ((unsigned)(gx + 1) < 1024u) b = __ldg(p + 1);
        }
        vx[k] = a; vy[k] = b;
    }
}

__device__ __forceinline__ void stage_store(char* plane, int tid,
                                            const float* vx, const float* vy)
{
    #pragma unroll
    for (int k = 0; k < NK; ++k) {
        int t = tid + 256 * k;
        if (t < NTASK) {
            int c  = t / 130;
            int s2 = t - c * 130;
            uint2 ov;
            ov.x = f2tf32(vx[k]);
            ov.y = f2tf32(vy[k]);
            *(uint2*)(plane + c * PITCH_B + s2 * 8) = ov;
        }
    }
}

// ---------------------------------------------------------------------------
// Kernel 2: tf32 mma.sync implicit-GEMM conv (32ch->16ch, 4x4, pad 2).
// grid = (5, 29), 256 threads. Row-pipelined plane ring; staging loads are
// issued before the MMA loop so DRAM latency hides behind tensor work.
// ---------------------------------------------------------------------------
__global__ void __launch_bounds__(256, 1)
conv_kernel(const float* __restrict__ data)
{
    extern __shared__ char smem[];
    float* sB = (float*)smem;
    const uint32_t sbase = smem_u32(smem);
    const int tid  = threadIdx.x;
    const int warp = tid >> 5;
    const int lane = tid & 31;

    const int x0 = blockIdx.x * XT;
    const int y0 = blockIdx.y * ROWS_PER;
    const int y1 = min(y0 + ROWS_PER - 1, TEXP - 1);

    // B fragments -> smem
    for (int i = tid; i < 8192; i += 256) sB[i] = g_filtB[i];

    // prologue: planes for data rows y0-2 .. y0+1   (slot(Y) = (Y+10)%5)
    {
        float vx[NK], vy[NK];
        for (int pp = 0; pp < 4; ++pp) {
            int Y = y0 - 2 + pp;
            stage_load(data, x0, Y, tid, vx, vy);
            stage_store(smem + PL_OFF + ((Y + 10) % 5) * PLANE_B, tid, vx, vy);
        }
    }
    __syncthreads();

    // per-thread fragment constants
    const int kk  = lane & 3;
    const int r   = lane >> 2;
    const int hib = kk >> 1;             // selects group g = 2j + hib
    const uint32_t xoff  = (uint32_t)(warp * 32 + ((kk & 1) << 1) + r) * 4u;
    const uint32_t bfrag = sbase + (uint32_t)(lane << 4);

    for (int y = y0; y <= y1; ++y) {
        // ---- issue staged loads for data row y+2 (latency hidden by MMA) ----
        float vx[NK], vy[NK];
        const int Yst = y + 2;
        stage_load(data, x0, Yst, tid, vx, vy);

        const uint32_t pE0 = sbase + PL_OFF + (uint32_t)((y - 2 + hib + 10) % 5) * PLANE_B + xoff;
        const uint32_t pO0 = sbase + PL_OFF + (uint32_t)((y     + hib + 10) % 5) * PLANE_B + xoff;

        float acc[16];
        #pragma unroll
        for (int i = 0; i < 16; ++i) acc[i] = 0.f;

        uint32_t pE = pE0, pO = pO0, bp = bfrag;

        #pragma unroll 8
        for (int u = 0; u < 32; ++u) {
            uint32_t a0, a1, a2, a3, b0, b1, b2, b3;

            // ---- kstep j = 2u (ky = hib), channel c = u ----
            asm("ld.shared.v4.b32 {%0,%1,%2,%3}, [%4];"
                : "=r"(b0), "=r"(b1), "=r"(b2), "=r"(b3) : "r"(bp));
            LDS32(a0, pE);       LDS32(a2, pE + 4);
            LDS32(a1, pE + 32);  LDS32(a3, pE + 36);
            MMA8(acc + 0, a0, a1, a2, a3, b0, b1);
            MMA8(acc + 4, a0, a1, a2, a3, b2, b3);
            LDS32(a0, pE + 64);  LDS32(a2, pE + 68);
            LDS32(a1, pE + 96);  LDS32(a3, pE + 100);
            MMA8(acc + 8,  a0, a1, a2, a3, b0, b1);
            MMA8(acc + 12, a0, a1, a2, a3, b2, b3);

            // ---- kstep j = 2u+1 (ky = 2 + hib), same channel ----
            asm("ld.shared.v4.b32 {%0,%1,%2,%3}, [%4];"
                : "=r"(b0), "=r"(b1), "=r"(b2), "=r"(b3) : "r"(bp + 512));
            LDS32(a0, pO);       LDS32(a2, pO + 4);
            LDS32(a1, pO + 32);  LDS32(a3, pO + 36);
            MMA8(acc + 0, a0, a1, a2, a3, b0, b1);
            MMA8(acc + 4, a0, a1, a2, a3, b2, b3);
            LDS32(a0, pO + 64);  LDS32(a2, pO + 68);
            LDS32(a1, pO + 96);  LDS32(a3, pO + 100);
            MMA8(acc + 8,  a0, a1, a2, a3, b0, b1);
            MMA8(acc + 12, a0, a1, a2, a3, b2, b3);

            pE += PITCH_B;
            pO += PITCH_B;
            bp += 1024;
        }

        // ---- store row y (channel-last); C frag rows r/r+8, cols 2kk,2kk+1
        {
            const int xb = x0 + warp * 32 + r;
            const size_t rowbase = (size_t)y * TEXP;
            #pragma unroll
            for (int mt = 0; mt < 2; ++mt) {
                #pragma unroll
                for (int rr = 0; rr < 2; ++rr) {
                    int x = xb + mt * 16 + rr * 8;
                    if (x < TEXP) {
                        float* dst = g_tex + (rowbase + x) * OUTC + 2 * kk;
                        *(float2*)dst       = make_float2(acc[mt * 8 + rr * 2],
                                                          acc[mt * 8 + rr * 2 + 1]);
                        *(float2*)(dst + 8) = make_float2(acc[mt * 8 + 4 + rr * 2],
                                                          acc[mt * 8 + 4 + rr * 2 + 1]);
                    }
                }
            }
        }
        __syncthreads();    // all reads of ring slot (y+2)%5's old row done
        stage_store(smem + PL_OFF + ((Yst + 10) % 5) * PLANE_B, tid, vx, vy);
        __syncthreads();    // plane y+2 committed for next row
    }
}

// ---------------------------------------------------------------------------
// Kernel 3: bilinear grid sample (border, align_corners=False)
// ---------------------------------------------------------------------------
__global__ void sample_kernel(const float* __restrict__ uv, float* __restrict__ out)
{
    int p = blockIdx.x * blockDim.x + threadIdx.x;
    if (p >= TEXD * TEXD) return;

    float x = uv[p];
    float y = uv[(TEXD * TEXD) + p];

    float ix = ((x + 1.f) * (float)TEXP - 1.f) * 0.5f;
    float iy = ((y + 1.f) * (float)TEXP - 1.f) * 0.5f;
    ix = fminf(fmaxf(ix, 0.f), (float)(TEXP - 1));
    iy = fminf(fmaxf(iy, 0.f), (float)(TEXP - 1));

    float fx0 = floorf(ix), fy0 = floorf(iy);
    float wx = ix - fx0, wy = iy - fy0;
    int xi0 = (int)fx0, yi0 = (int)fy0;
    int xi1 = min(xi0 + 1, TEXP - 1);
    int yi1 = min(yi0 + 1, TEXP - 1);

    const float4* t00 = (const float4*)&g_tex[(yi0 * TEXP + xi0) * OUTC];
    const float4* t01 = (const float4*)&g_tex[(yi0 * TEXP + xi1) * OUTC];
    const float4* t10 = (const float4*)&g_tex[(yi1 * TEXP + xi0) * OUTC];
    const float4* t11 = (const float4*)&g_tex[(yi1 * TEXP + xi1) * OUTC];

    float w00 = (1.f - wx) * (1.f - wy);
    float w01 = wx * (1.f - wy);
    float w10 = (1.f - wx) * wy;
    float w11 = wx * wy;

    #pragma unroll
    for (int v = 0; v < 4; ++v) {
        float4 a = t00[v], b = t01[v], cc = t10[v], dd = t11[v];
        float r0 = a.x * w00 + b.x * w01 + cc.x * w10 + dd.x * w11;
        float r1 = a.y * w00 + b.y * w01 + cc.y * w10 + dd.y * w11;
        float r2 = a.z * w00 + b.z * w01 + cc.z * w10 + dd.z * w11;
        float r3 = a.w * w00 + b.w * w01 + cc.w * w10 + dd.w * w11;
        out[(v * 4 + 0) * (TEXD * TEXD) + p] = r0;
        out[(v * 4 + 1) * (TEXD * TEXD) + p] = r1;
        out[(v * 4 + 2) * (TEXD * TEXD) + p] = r2;
        out[(v * 4 + 3) * (TEXD * TEXD) + p] = r3;
    }
}

// ---------------------------------------------------------------------------
extern "C" void kernel_launch(void* const* d_in, const int* in_sizes, int n_in,
                              void* d_out, int out_size)
{
    const float* expr = (const float*)d_in[0];
    const float* uv   = (const float*)d_in[2];
    const float* data = (const float*)d_in[3];
    const float* W1   = (const float*)d_in[4];
    const float* b1   = (const float*)d_in[5];
    const float* W2   = (const float*)d_in[6];
    const float* b2   = (const float*)d_in[7];
    const float* W3   = (const float*)d_in[8];
    const float* b3   = (const float*)d_in[9];
    float* out = (float*)d_out;

    cudaFuncSetAttribute(conv_kernel, cudaFuncAttributeMaxDynamicSharedMemorySize,
                         SMEM_CONV);

    mlp12_kernel<<<1, 128>>>(expr, W1, b1, W2, b2);
    filt_kernel<<<1024, 256>>>(W3, b3);

    dim3 cgrid(XSTRIPS, YSPLIT);
    conv_kernel<<<cgrid, 256, SMEM_CONV>>>(data);

    sample_kernel<<<(TEXD * TEXD + 255) / 256, 256>>>(uv, out);
}

// round 11
// speedup vs baseline: 3.1916x; 1.7873x over previous
#include <cuda_runtime.h>
#include <cuda_fp16.h>
#include <cstdint>

#define TEXD   1024
#define TEXP   1025
#define OUTC   16
#define INC    32

// ---- conv GEMM geometry (fp16 m16n8k16, k = channel) ----
#define XT        256          // pixels per x-strip (8 warps x 32 px)
#define XSTRIPS   5
#define YSPLIT    29
#define ROWS_PER  36           // 29*36 = 1044 >= 1025
#define SROWS     260          // staged x positions per plane
#define XSTRIDE   48           // bytes per x position (32 B data + 16 pad; 12 words)
#define CGS       12480        // 260 * 48 : bytes per channel-group within plane
#define PLANE_B   24960        // 2 channel-groups
#define NPLANES   5
#define PL_OFF    16384        // B fragments occupy [0, 16384)
#define SMEM_CONV (PL_OFF + NPLANES * PLANE_B)   // 141184 B
#define NTASK     520          // 2 cg * 260 x per plane
#define NKS       3

__device__ unsigned short g_filtB[8192];    // prepacked fp16 B fragments
__device__ float g_h2[64];
__device__ float g_tex[TEXP * TEXP * OUTC]; // [y][x][o] channel-last

// ------------------------------ helpers -----------------------------------
__device__ __forceinline__ uint32_t smem_u32(const void* p) {
    uint32_t a;
    asm("{ .reg .u64 t; cvta.to.shared.u64 t, %1; cvt.u32.u64 %0, t; }" : "=r"(a) : "l"(p));
    return a;
}

#define MMA16(C, A0, A1, A2, A3, B0, B1)                                      \
    asm volatile("mma.sync.aligned.m16n8k16.row.col.f32.f16.f16.f32 "         \
                 "{%0,%1,%2,%3}, {%4,%5,%6,%7}, {%8,%9}, {%0,%1,%2,%3};"      \
                 : "+f"((C)[0]), "+f"((C)[1]), "+f"((C)[2]), "+f"((C)[3])     \
                 : "r"(A0), "r"(A1), "r"(A2), "r"(A3), "r"(B0), "r"(B1))

#define LDS32(dst, addr) \
    asm("ld.shared.b32 %0, [%1];" : "=r"(dst) : "r"(addr))

// ---------------------------------------------------------------------------
// Kernel 1a: MLP layers 1-2
// ---------------------------------------------------------------------------
__global__ void mlp12_kernel(const float* __restrict__ expr,
                             const float* __restrict__ W1, const float* __restrict__ b1,
                             const float* __restrict__ W2, const float* __restrict__ b2)
{
    __shared__ float sx[76];
    __shared__ float h1[128];
    const int tid = threadIdx.x;

    if (tid < 76) sx[tid] = expr[tid];
    __syncthreads();
    if (tid < 128) {
        float a = b1[tid];
        const float* w = W1 + tid * 76;
        #pragma unroll 4
        for (int k = 0; k < 76; ++k) a = fmaf(w[k], sx[k], a);
        h1[tid] = (a >= 0.f) ? a : 0.02f * a;
    }
    __syncthreads();
    if (tid < 64) {
        float a = b2[tid];
        const float* w = W2 + tid * 128;
        #pragma unroll 4
        for (int k = 0; k < 128; ++k) a = fmaf(w[k], h1[k], a);
        g_h2[tid] = (a >= 0.f) ? a : 0.02f * a;
    }
}

// ---------------------------------------------------------------------------
// Kernel 1b: MLP layer 3 -> fp16 B fragments for m16n8k16, k = channel.
// m = o*512 + c*16 + ky*4 + kx.  kstep j = (ky*4+kx)*2 + (c>>4), k = c&15.
// Thread ln = ((o&7)<<2)|tg holds (per kstep) uint32x4:
//   cmp0 = {W[o=g][k=2tg], W[g][2tg+1]}      (b0, n-tile o0-7)
//   cmp1 = {W[g][2tg+8],  W[g][2tg+9]}       (b1)
//   cmp2 = {W[g+8][2tg],  W[g+8][2tg+1]}     (b0, n-tile o8-15)
//   cmp3 = {W[g+8][2tg+8],W[g+8][2tg+9]}     (b1)
// ---------------------------------------------------------------------------
__global__ void filt_kernel(const float* __restrict__ W3, const float* __restrict__ b3)
{
    const int lane = threadIdx.x & 31;
    const int warp = threadIdx.x >> 5;
    const int m    = blockIdx.x * 8 + warp;

    const float* w = W3 + m * 64;
    float v = w[lane] * g_h2[lane] + w[lane + 32] * g_h2[lane + 32];
    #pragma unroll
    for (int s = 16; s > 0; s >>= 1) v += __shfl_xor_sync(0xFFFFFFFFu, v, s);

    if (lane == 0) {
        float a = tanhf(v + b3[m]);
        int o  = m >> 9;
        int r  = m & 511;
        int c  = r >> 4;
        int t  = r & 15;              // ky*4 + kx
        int j  = (t << 1) | (c >> 4);
        int ck = c & 15;
        int tg = (ck >> 1) & 3;
        int cmp = ((ck >> 3) & 1) | ((o >> 3) << 1);
        int ln  = ((o & 7) << 2) | tg;
        int idx = ((((j * 32 + ln) << 2) | cmp) << 1) | (ck & 1);
        g_filtB[idx] = __half_as_ushort(__float2half_rn(a));
    }
}

// ---------------------------------------------------------------------------
// staging: one data row Y -> fp16 plane. Task t: cg = t>=260, s = t-260*cg.
// Plane layout: [cg][s][16 fp16 channels, natural order], stride 48 B per s.
// ---------------------------------------------------------------------------
__device__ __forceinline__ void stage_load(const float* __restrict__ data,
                                           int x0, int Y, int tid,
                                           uint32_t st[NKS][8])
{
    const bool yok = (unsigned)Y < 1024u;
    #pragma unroll
    for (int k = 0; k < NKS; ++k) {
        int t = tid + 256 * k;
        bool ok = (t < NTASK) && yok;
        int cg = (t >= 260) ? 1 : 0;
        int s  = t - 260 * cg;
        int gx = x0 - 2 + s;
        bool xok = ok && ((unsigned)gx < 1024u);
        float v[16];
        #pragma unroll
        for (int i = 0; i < 16; ++i) {
            const float* p = data + (((size_t)(cg * 16 + i)) << 20)
                                  + (((size_t)(Y & 1023)) << 10) + (gx & 1023);
            v[i] = xok ? __ldg(p) : 0.f;
        }
        #pragma unroll
        for (int i = 0; i < 8; ++i) {
            __half2 h = __floats2half2_rn(v[2 * i], v[2 * i + 1]);
            st[k][i] = *(uint32_t*)&h;
        }
    }
}

__device__ __forceinline__ void stage_store(char* plane, int tid,
                                            const uint32_t st[NKS][8])
{
    #pragma unroll
    for (int k = 0; k < NKS; ++k) {
        int t = tid + 256 * k;
        if (t < NTASK) {
            int cg = (t >= 260) ? 1 : 0;
            int s  = t - 260 * cg;
            char* p = plane + cg * CGS + s * XSTRIDE;
            *(uint4*)p        = make_uint4(st[k][0], st[k][1], st[k][2], st[k][3]);
            *(uint4*)(p + 16) = make_uint4(st[k][4], st[k][5], st[k][6], st[k][7]);
        }
    }
}

// ---------------------------------------------------------------------------
// Kernel 2: fp16 m16n8k16 implicit-GEMM conv (32ch->16ch, 4x4, pad 2).
// grid = (5, 29), 256 threads. Warp w: pixels [x0+32w, x0+32w+32).
// Per row: 32 ksteps = 16 taps x 2 channel-groups; plane ring of 5 rows.
// A loads conflict-free (stride 12 words: 12g+tg bijective mod 32).
// ---------------------------------------------------------------------------
__global__ void __launch_bounds__(256, 1)
conv_kernel(const float* __restrict__ data)
{
    extern __shared__ char smem[];
    const uint32_t sbase = smem_u32(smem);
    const int tid  = threadIdx.x;
    const int warp = tid >> 5;
    const int lane = tid & 31;

    const int x0 = blockIdx.x * XT;
    const int y0 = blockIdx.y * ROWS_PER;
    const int y1 = min(y0 + ROWS_PER - 1, TEXP - 1);

    // B fragments -> smem (16 KB)
    {
        const uint4* src = (const uint4*)g_filtB;
        uint4* dst = (uint4*)smem;
        #pragma unroll
        for (int i = tid; i < 1024; i += 256) dst[i] = src[i];
    }

    // prologue: planes for data rows y0-2 .. y0+1   (slot(Y) = (Y+10)%5)
    {
        uint32_t st[NKS][8];
        for (int pp = 0; pp < 4; ++pp) {
            int Y = y0 - 2 + pp;
            stage_load(data, x0, Y, tid, st);
            stage_store(smem + PL_OFF + ((Y + 10) % 5) * PLANE_B, tid, st);
        }
    }
    __syncthreads();

    const int tg = lane & 3;
    const int g  = lane >> 2;
    const uint32_t tconst = (uint32_t)((warp * 32 + g) * XSTRIDE + 4 * tg);

    for (int y = y0; y <= y1; ++y) {
        // issue staged loads for data row y+2 (latency hidden by MMA work)
        uint32_t st[NKS][8];
        const int Yst = y + 2;
        stage_load(data, x0, Yst, tid, st);

        uint32_t pb[4];
        #pragma unroll
        for (int ky = 0; ky < 4; ++ky)
            pb[ky] = sbase + PL_OFF + (uint32_t)(((y - 2 + ky + 10) % 5) * PLANE_B) + tconst;

        float aA[4] = {0.f, 0.f, 0.f, 0.f};
        float aB[4] = {0.f, 0.f, 0.f, 0.f};
        float aC[4] = {0.f, 0.f, 0.f, 0.f};
        float aD[4] = {0.f, 0.f, 0.f, 0.f};

        uint32_t bp = sbase + (uint32_t)(lane << 4);

        #pragma unroll 4
        for (int t16 = 0; t16 < 16; ++t16) {
            const uint32_t base = pb[t16 >> 2] + (uint32_t)((t16 & 3) * XSTRIDE);
            #pragma unroll
            for (int cg = 0; cg < 2; ++cg) {
                const uint32_t ad = base + (uint32_t)(cg * CGS);
                uint32_t a0, a1, a2, a3, a4, a5, a6, a7, b0, b1, b2, b3;
                asm("ld.shared.v4.b32 {%0,%1,%2,%3}, [%4];"
                    : "=r"(b0), "=r"(b1), "=r"(b2), "=r"(b3) : "r"(bp));
                LDS32(a0, ad);          LDS32(a2, ad + 16);
                LDS32(a1, ad + 384);    LDS32(a3, ad + 400);
                LDS32(a4, ad + 768);    LDS32(a6, ad + 784);
                LDS32(a5, ad + 1152);   LDS32(a7, ad + 1168);
                MMA16(aA, a0, a1, a2, a3, b0, b1);
                MMA16(aB, a0, a1, a2, a3, b2, b3);
                MMA16(aC, a4, a5, a6, a7, b0, b1);
                MMA16(aD, a4, a5, a6, a7, b2, b3);
                bp += 512;
            }
        }

        // store row y (channel-last); thread: pixels xb+{0,8,16,24},
        // channels {2tg,2tg+1} and {2tg+8,2tg+9}
        {
            const int xb = x0 + warp * 32 + g;
            const size_t rowb = (size_t)y * TEXP;
            #pragma unroll
            for (int pi = 0; pi < 4; ++pi) {
                int x = xb + pi * 8;
                if (x < TEXP) {
                    const float* A = (pi < 2) ? aA : aC;
                    const float* B = (pi < 2) ? aB : aD;
                    int o2 = (pi & 1) << 1;
                    float* dst = g_tex + (rowb + x) * OUTC + 2 * tg;
                    *(float2*)dst       = make_float2(A[o2], A[o2 + 1]);
                    *(float2*)(dst + 8) = make_float2(B[o2], B[o2 + 1]);
                }
            }
        }
        __syncthreads();    // all reads of ring slot (y+2)%5's old row done
        stage_store(smem + PL_OFF + ((Yst + 10) % 5) * PLANE_B, tid, st);
        __syncthreads();    // plane y+2 committed
    }
}

// ---------------------------------------------------------------------------
// Kernel 3: bilinear grid sample (border, align_corners=False)
// ---------------------------------------------------------------------------
__global__ void sample_kernel(const float* __restrict__ uv, float* __restrict__ out)
{
    int p = blockIdx.x * blockDim.x + threadIdx.x;
    if (p >= TEXD * TEXD) return;

    float x = uv[p];
    float y = uv[(TEXD * TEXD) + p];

    float ix = ((x + 1.f) * (float)TEXP - 1.f) * 0.5f;
    float iy = ((y + 1.f) * (float)TEXP - 1.f) * 0.5f;
    ix = fminf(fmaxf(ix, 0.f), (float)(TEXP - 1));
    iy = fminf(fmaxf(iy, 0.f), (float)(TEXP - 1));

    float fx0 = floorf(ix), fy0 = floorf(iy);
    float wx = ix - fx0, wy = iy - fy0;
    int xi0 = (int)fx0, yi0 = (int)fy0;
    int xi1 = min(xi0 + 1, TEXP - 1);
    int yi1 = min(yi0 + 1, TEXP - 1);

    const float4* t00 = (const float4*)&g_tex[(yi0 * TEXP + xi0) * OUTC];
    const float4* t01 = (const float4*)&g_tex[(yi0 * TEXP + xi1) * OUTC];
    const float4* t10 = (const float4*)&g_tex[(yi1 * TEXP + xi0) * OUTC];
    const float4* t11 = (const float4*)&g_tex[(yi1 * TEXP + xi1) * OUTC];

    float w00 = (1.f - wx) * (1.f - wy);
    float w01 = wx * (1.f - wy);
    float w10 = (1.f - wx) * wy;
    float w11 = wx * wy;

    #pragma unroll
    for (int v = 0; v < 4; ++v) {
        float4 a = t00[v], b = t01[v], cc = t10[v], dd = t11[v];
        float r0 = a.x * w00 + b.x * w01 + cc.x * w10 + dd.x * w11;
        float r1 = a.y * w00 + b.y * w01 + cc.y * w10 + dd.y * w11;
        float r2 = a.z * w00 + b.z * w01 + cc.z * w10 + dd.z * w11;
        float r3 = a.w * w00 + b.w * w01 + cc.w * w10 + dd.w * w11;
        out[(v * 4 + 0) * (TEXD * TEXD) + p] = r0;
        out[(v * 4 + 1) * (TEXD * TEXD) + p] = r1;
        out[(v * 4 + 2) * (TEXD * TEXD) + p] = r2;
        out[(v * 4 + 3) * (TEXD * TEXD) + p] = r3;
    }
}

// ---------------------------------------------------------------------------
extern "C" void kernel_launch(void* const* d_in, const int* in_sizes, int n_in,
                              void* d_out, int out_size)
{
    const float* expr = (const float*)d_in[0];
    const float* uv   = (const float*)d_in[2];
    const float* data = (const float*)d_in[3];
    const float* W1   = (const float*)d_in[4];
    const float* b1   = (const float*)d_in[5];
    const float* W2   = (const float*)d_in[6];
    const float* b2   = (const float*)d_in[7];
    const float* W3   = (const float*)d_in[8];
    const float* b3   = (const float*)d_in[9];
    float* out = (float*)d_out;

    cudaFuncSetAttribute(conv_kernel, cudaFuncAttributeMaxDynamicSharedMemorySize,
                         SMEM_CONV);

    mlp12_kernel<<<1, 128>>>(expr, W1, b1, W2, b2);
    filt_kernel<<<1024, 256>>>(W3, b3);

    dim3 cgrid(XSTRIPS, YSPLIT);
    conv_kernel<<<cgrid, 256, SMEM_CONV>>>(data);

    sample_kernel<<<(TEXD * TEXD + 255) / 256, 256>>>(uv, out);
}

// round 14
// speedup vs baseline: 4.4652x; 1.3990x over previous
#include <cuda_runtime.h>
#include <cuda_fp16.h>
#include <cstdint>

#define TEXD   1024
#define TEXP   1025
#define OUTC   16
#define INC    32

// ---- conv GEMM geometry (fp16 m16n8k16, k = channel, row-pair) ----
#define XT        256          // pixels per x-strip (8 warps x 32 px)
#define XSTRIPS   5
#define YSPLIT    29
#define ROWS_PER  36           // 29*36 = 1044 >= 1025
#define SROWS     260          // staged x positions per plane
#define XSTRIDE   48           // bytes per x position (32 B data + 16 pad)
#define CGS       12480        // 260 * 48 : bytes per channel-group
#define PLANE_B   24960        // 2 channel-groups
#define NPLANES   7
#define PL_OFF    16384        // B fragments occupy [0, 16384)
#define SMEM_CONV (PL_OFF + NPLANES * PLANE_B)   // 191104 B
#define NTASK     520          // 2 cg * 260 x per plane
#define NKS       3
#define SLOT(Y)   (((Y) + 7) % 7)

__device__ unsigned short g_filtB[8192];      // prepacked fp16 B fragments
__device__ float  g_h2[64];
__device__ __half g_tex[TEXP * TEXP * OUTC];  // [y][x][o] channel-last fp16

// ------------------------------ helpers -----------------------------------
__device__ __forceinline__ uint32_t smem_u32(const void* p) {
    uint32_t a;
    asm("{ .reg .u64 t; cvta.to.shared.u64 t, %1; cvt.u32.u64 %0, t; }" : "=r"(a) : "l"(p));
    return a;
}

#define MMA16(C, A0, A1, A2, A3, B0, B1)                                      \
    asm volatile("mma.sync.aligned.m16n8k16.row.col.f32.f16.f16.f32 "         \
                 "{%0,%1,%2,%3}, {%4,%5,%6,%7}, {%8,%9}, {%0,%1,%2,%3};"      \
                 : "+f"((C)[0]), "+f"((C)[1]), "+f"((C)[2]), "+f"((C)[3])     \
                 : "r"(A0), "r"(A1), "r"(A2), "r"(A3), "r"(B0), "r"(B1))

#define LDS32(dst, addr) \
    asm("ld.shared.b32 %0, [%1];" : "=r"(dst) : "r"(addr))

// ---------------------------------------------------------------------------
// Kernel 1a: MLP layers 1-2
// ---------------------------------------------------------------------------
__global__ void mlp12_kernel(const float* __restrict__ expr,
                             const float* __restrict__ W1, const float* __restrict__ b1,
                             const float* __restrict__ W2, const float* __restrict__ b2)
{
    __shared__ float sx[76];
    __shared__ float h1[128];
    const int tid = threadIdx.x;

    if (tid < 76) sx[tid] = expr[tid];
    __syncthreads();
    if (tid < 128) {
        float a = b1[tid];
        const float* w = W1 + tid * 76;
        #pragma unroll 4
        for (int k = 0; k < 76; ++k) a = fmaf(w[k], sx[k], a);
        h1[tid] = (a >= 0.f) ? a : 0.02f * a;
    }
    __syncthreads();
    if (tid < 64) {
        float a = b2[tid];
        const float* w = W2 + tid * 128;
        #pragma unroll 4
        for (int k = 0; k < 128; ++k) a = fmaf(w[k], h1[k], a);
        g_h2[tid] = (a >= 0.f) ? a : 0.02f * a;
    }
}

// ---------------------------------------------------------------------------
// Kernel 1b: MLP layer 3 -> fp16 B fragments (mapping verified, rounds 8-11)
// ---------------------------------------------------------------------------
__global__ void filt_kernel(const float* __restrict__ W3, const float* __restrict__ b3)
{
    const int lane = threadIdx.x & 31;
    const int warp = threadIdx.x >> 5;
    const int m    = blockIdx.x * 8 + warp;

    const float* w = W3 + m * 64;
    float v = w[lane] * g_h2[lane] + w[lane + 32] * g_h2[lane + 32];
    #pragma unroll
    for (int s = 16; s > 0; s >>= 1) v += __shfl_xor_sync(0xFFFFFFFFu, v, s);

    if (lane == 0) {
        float a = tanhf(v + b3[m]);
        int o  = m >> 9;
        int r  = m & 511;
        int c  = r >> 4;
        int t  = r & 15;              // ky*4 + kx
        int j  = (t << 1) | (c >> 4);
        int ck = c & 15;
        int tg = (ck >> 1) & 3;
        int cmp = ((ck >> 3) & 1) | ((o >> 3) << 1);
        int ln  = ((o & 7) << 2) | tg;
        int idx = ((((j * 32 + ln) << 2) | cmp) << 1) | (ck & 1);
        g_filtB[idx] = __half_as_ushort(__float2half_rn(a));
    }
}

// ---------------------------------------------------------------------------
// staging (verified rounds 8-11): one data row Y -> fp16 plane.
// ---------------------------------------------------------------------------
__device__ __forceinline__ void stage_load(const float* __restrict__ data,
                                           int x0, int Y, int tid,
                                           uint32_t st[NKS][8])
{
    const bool yok = (unsigned)Y < 1024u;
    #pragma unroll
    for (int k = 0; k < NKS; ++k) {
        int t = tid + 256 * k;
        bool ok = (t < NTASK) && yok;
        int cg = (t >= 260) ? 1 : 0;
        int s  = t - 260 * cg;
        int gx = x0 - 2 + s;
        bool xok = ok && ((unsigned)gx < 1024u);
        float v[16];
        #pragma unroll
        for (int i = 0; i < 16; ++i) {
            const float* p = data + (((size_t)(cg * 16 + i)) << 20)
                                  + (((size_t)(Y & 1023)) << 10) + (gx & 1023);
            v[i] = xok ? __ldg(p) : 0.f;
        }
        #pragma unroll
        for (int i = 0; i < 8; ++i) {
            __half2 h = __floats2half2_rn(v[2 * i], v[2 * i + 1]);
            st[k][i] = *(uint32_t*)&h;
        }
    }
}

__device__ __forceinline__ void stage_store(char* plane, int tid,
                                            const uint32_t st[NKS][8])
{
    #pragma unroll
    for (int k = 0; k < NKS; ++k) {
        int t = tid + 256 * k;
        if (t < NTASK) {
            int cg = (t >= 260) ? 1 : 0;
            int s  = t - 260 * cg;
            char* p = plane + cg * CGS + s * XSTRIDE;
            *(uint4*)p        = make_uint4(st[k][0], st[k][1], st[k][2], st[k][3]);
            *(uint4*)(p + 16) = make_uint4(st[k][4], st[k][5], st[k][6], st[k][7]);
        }
    }
}

// ---------------------------------------------------------------------------
// Kernel 2: fp16 m16n8k16 implicit-GEMM conv, ROW-PAIR version.
// Pair (y, y+1): A fragment from plane p=y-2..y+2 serves tap ky=p-(y-2) of
// row y and ky-1 of row y+1 -> A loaded once, used twice. One barrier/pair.
// Ring: reads slots y-2..y+2, writes y+3,y+4 (≡ y-4,y-3 mod 7) — disjoint.
// ---------------------------------------------------------------------------
__global__ void __launch_bounds__(256, 1)
conv_kernel(const float* __restrict__ data)
{
    extern __shared__ char smem[];
    const uint32_t sbase = smem_u32(smem);
    const int tid  = threadIdx.x;
    const int warp = tid >> 5;
    const int lane = tid & 31;

    const int x0 = blockIdx.x * XT;
    const int y0 = blockIdx.y * ROWS_PER;
    const int y1 = min(y0 + ROWS_PER - 1, TEXP - 1);

    // B fragments -> smem (16 KB)
    {
        const uint4* src = (const uint4*)g_filtB;
        uint4* dst = (uint4*)smem;
        #pragma unroll
        for (int i = tid; i < 1024; i += 256) dst[i] = src[i];
    }

    // prologue: stage planes for data rows y0-2 .. y0+2 (5 planes)
    {
        uint32_t st[NKS][8];
        for (int pp = 0; pp < 5; ++pp) {
            int Y = y0 - 2 + pp;
            stage_load(data, x0, Y, tid, st);
            stage_store(smem + PL_OFF + SLOT(Y) * PLANE_B, tid, st);
        }
    }
    __syncthreads();

    const int tg = lane & 3;
    const int g  = lane >> 2;
    const uint32_t tconst = (uint32_t)((warp * 32 + g) * XSTRIDE + 4 * tg);
    const uint32_t bln    = sbase + (uint32_t)(lane << 4);

    for (int y = y0; y <= y1; y += 2) {
        // issue staged loads for data rows y+3, y+4 (hidden behind MMA)
        uint32_t stA[NKS][8], stB[NKS][8];
        stage_load(data, x0, y + 3, tid, stA);
        stage_load(data, x0, y + 4, tid, stB);

        uint32_t pb[5];
        #pragma unroll
        for (int p = 0; p < 5; ++p)
            pb[p] = sbase + PL_OFF + (uint32_t)(SLOT(y - 2 + p) * PLANE_B) + tconst;

        float accY[16], accZ[16];
        #pragma unroll
        for (int i = 0; i < 16; ++i) { accY[i] = 0.f; accZ[i] = 0.f; }

        #pragma unroll
        for (int p = 0; p < 5; ++p) {
            #pragma unroll
            for (int kx = 0; kx < 4; ++kx) {
                #pragma unroll
                for (int cg = 0; cg < 2; ++cg) {
                    const uint32_t ad = pb[p] + (uint32_t)(kx * XSTRIDE + cg * CGS);
                    uint32_t a0, a1, a2, a3, a4, a5, a6, a7;
                    LDS32(a0, ad);          LDS32(a2, ad + 16);
                    LDS32(a1, ad + 384);    LDS32(a3, ad + 400);
                    LDS32(a4, ad + 768);    LDS32(a6, ad + 784);
                    LDS32(a5, ad + 1152);   LDS32(a7, ad + 1168);

                    if (p < 4) {   // row y, tap ky = p
                        uint32_t b0, b1, b2, b3;
                        uint32_t bp = bln + (uint32_t)(((((p * 4 + kx) << 1) | cg)) * 512);
                        asm("ld.shared.v4.b32 {%0,%1,%2,%3}, [%4];"
                            : "=r"(b0), "=r"(b1), "=r"(b2), "=r"(b3) : "r"(bp));
                        MMA16(accY + 0,  a0, a1, a2, a3, b0, b1);
                        MMA16(accY + 4,  a0, a1, a2, a3, b2, b3);
                        MMA16(accY + 8,  a4, a5, a6, a7, b0, b1);
                        MMA16(accY + 12, a4, a5, a6, a7, b2, b3);
                    }
                    if (p > 0) {   // row y+1, tap ky = p-1
                        uint32_t b0, b1, b2, b3;
                        uint32_t bp = bln + (uint32_t)((((((p - 1) * 4 + kx) << 1) | cg)) * 512);
                        asm("ld.shared.v4.b32 {%0,%1,%2,%3}, [%4];"
                            : "=r"(b0), "=r"(b1), "=r"(b2), "=r"(b3) : "r"(bp));
                        MMA16(accZ + 0,  a0, a1, a2, a3, b0, b1);
                        MMA16(accZ + 4,  a0, a1, a2, a3, b2, b3);
                        MMA16(accZ + 8,  a4, a5, a6, a7, b0, b1);
                        MMA16(accZ + 12, a4, a5, a6, a7, b2, b3);
                    }
                }
            }
        }

        // epilogue (fp16 channel-last): thread = pixels xb+{0,8,16,24},
        // channels {2tg,2tg+1} and {2tg+8,2tg+9}
        {
            const int xb = x0 + warp * 32 + g;
            #pragma unroll
            for (int row = 0; row < 2; ++row) {
                const int yy = y + row;
                if (yy <= y1) {
                    const float* acc = row ? accZ : accY;
                    const size_t rowb = (size_t)yy * TEXP;
                    #pragma unroll
                    for (int pi = 0; pi < 4; ++pi) {
                        int x = xb + pi * 8;
                        if (x < TEXP) {
                            const float* A = (pi < 2) ? acc : acc + 8;
                            const float* B = (pi < 2) ? acc + 4 : acc + 12;
                            int o2 = (pi & 1) << 1;
                            __half* dst = g_tex + (rowb + x) * OUTC + 2 * tg;
                            *(__half2*)dst       = __floats2half2_rn(A[o2], A[o2 + 1]);
                            *(__half2*)(dst + 8) = __floats2half2_rn(B[o2], B[o2 + 1]);
                        }
                    }
                }
            }
        }

        // commit planes y+3, y+4 (slots disjoint from this pair's reads)
        stage_store(smem + PL_OFF + SLOT(y + 3) * PLANE_B, tid, stA);
        stage_store(smem + PL_OFF + SLOT(y + 4) * PLANE_B, tid, stB);
        __syncthreads();
    }
}

// ---------------------------------------------------------------------------
// Kernel 3: bilinear grid sample from fp16 texture (border, align=False)
// ---------------------------------------------------------------------------
__global__ void sample_kernel(const float* __restrict__ uv, float* __restrict__ out)
{
    int p = blockIdx.x * blockDim.x + threadIdx.x;
    if (p >= TEXD * TEXD) return;

    float x = uv[p];
    float y = uv[(TEXD * TEXD) + p];

    float ix = ((x + 1.f) * (float)TEXP - 1.f) * 0.5f;
    float iy = ((y + 1.f) * (float)TEXP - 1.f) * 0.5f;
    ix = fminf(fmaxf(ix, 0.f), (float)(TEXP - 1));
    iy = fminf(fmaxf(iy, 0.f), (float)(TEXP - 1));

    float fx0 = floorf(ix), fy0 = floorf(iy);
    float wx = ix - fx0, wy = iy - fy0;
    int xi0 = (int)fx0, yi0 = (int)fy0;
    int xi1 = min(xi0 + 1, TEXP - 1);
    int yi1 = min(yi0 + 1, TEXP - 1);

    const uint4* t00 = (const uint4*)&g_tex[(yi0 * TEXP + xi0) * OUTC];
    const uint4* t01 = (const uint4*)&g_tex[(yi0 * TEXP + xi1) * OUTC];
    const uint4* t10 = (const uint4*)&g_tex[(yi1 * TEXP + xi0) * OUTC];
    const uint4* t11 = (const uint4*)&g_tex[(yi1 * TEXP + xi1) * OUTC];

    float w00 = (1.f - wx) * (1.f - wy);
    float w01 = wx * (1.f - wy);
    float w10 = (1.f - wx) * wy;
    float w11 = wx * wy;

    float acc[16];
    #pragma unroll
    for (int i = 0; i < 16; ++i) acc[i] = 0.f;

    #pragma unroll
    for (int h = 0; h < 2; ++h) {      // two uint4 halves (8 channels each)
        uint4 c00 = t00[h], c01 = t01[h], c10 = t10[h], c11 = t11[h];
        const __half2* h00 = (const __half2*)&c00;
        const __half2* h01 = (const __half2*)&c01;
        const __half2* h10 = (const __half2*)&c10;
        const __half2* h11 = (const __half2*)&c11;
        #pragma unroll
        for (int j = 0; j < 4; ++j) {
            float2 f00 = __half22float2(h00[j]);
            float2 f01 = __half22float2(h01[j]);
            float2 f10 = __half22float2(h10[j]);
            float2 f11 = __half22float2(h11[j]);
            int v = h * 8 + j * 2;
            acc[v]     = f00.x * w00 + f01.x * w01 + f10.x * w10 + f11.x * w11;
            acc[v + 1] = f00.y * w00 + f01.y * w01 + f10.y * w10 + f11.y * w11;
        }
    }

    #pragma unroll
    for (int v = 0; v < 16; ++v)
        out[v * (TEXD * TEXD) + p] = acc[v];
}

// ---------------------------------------------------------------------------
extern "C" void kernel_launch(void* const* d_in, const int* in_sizes, int n_in,
                              void* d_out, int out_size)
{
    const float* expr = (const float*)d_in[0];
    const float* uv   = (const float*)d_in[2];
    const float* data = (const float*)d_in[3];
    const float* W1   = (const float*)d_in[4];
    const float* b1   = (const float*)d_in[5];
    const float* W2   = (const float*)d_in[6];
    const float* b2   = (const float*)d_in[7];
    const float* W3   = (const float*)d_in[8];
    const float* b3   = (const float*)d_in[9];
    float* out = (float*)d_out;

    cudaFuncSetAttribute(conv_kernel, cudaFuncAttributeMaxDynamicSharedMemorySize,
                         SMEM_CONV);

    mlp12_kernel<<<1, 128>>>(expr, W1, b1, W2, b2);
    filt_kernel<<<1024, 256>>>(W3, b3);

    dim3 cgrid(XSTRIPS, YSPLIT);
    conv_kernel<<<cgrid, 256, SMEM_CONV>>>(data);

    sample_kernel<<<(TEXD * TEXD + 255) / 256, 256>>>(uv, out);
}